// round 17
// baseline (speedup 1.0000x reference)
#include <cuda_runtime.h>
#include <cuda_fp16.h>

#define N_NODES 100000
#define N_EDGES 1600000
#define IN_F    128
#define OUT_F   64
#define NEG_SLOPE 0.2f
#define SLOT_LOG 7                         // 128 slots per dst row (max indeg << 128)
#define GEMM_TILE 64
#define GEMM_TILES ((N_NODES + GEMM_TILE - 1) / GEMM_TILE)      // 1563
#define GEMM_GRID 592
#define APAD 136   // padded half-row stride (conflict-free ldmatrix)

// ---------------- device scratch (static, allocation-free) ----------------
__device__ __half   g_h[N_NODES * OUT_F];     // fp16 payload: h * outnorm
__device__ __half   g_x[N_NODES * OUT_F];
__device__ __half   g_y[N_NODES * OUT_F];
__device__ float    g_el[N_NODES];
__device__ float    g_er[N_NODES];
__device__ float    g_scfin[N_NODES];         // hop1 cache: innorm/denom
__device__ float    g_outnorm[N_NODES];
__device__ float    g_innorm[N_NODES];        // after hop1: scmid
__device__ unsigned short g_rank[N_EDGES];    // edge's within-dst-row rank
__device__ int2     g_pack[N_NODES << SLOT_LOG];  // fixed-stride CSR {src, ee_bits}

// single zero-init region: [outdeg | indeg]
__device__ int      g_zbuf[2 * N_NODES];
#define G_OUTDEG (g_zbuf)
#define G_INDEG  (g_zbuf + N_NODES)
#define ZBUF_BYTES (2 * N_NODES * sizeof(int))

__device__ __forceinline__ unsigned smemu(const void* p) {
    return (unsigned)__cvta_generic_to_shared(p);
}

// ---------------- K1: degrees + per-edge rank (4 edges/thread) ------------
__global__ void k_deg(const int4* __restrict__ src4, const int4* __restrict__ dst4) {
    int i = blockIdx.x * blockDim.x + threadIdx.x;
    if (i >= N_EDGES / 4) return;
    int4 s = __ldg(src4 + i);
    int4 d = __ldg(dst4 + i);
    atomicAdd(&G_OUTDEG[s.x], 1);
    atomicAdd(&G_OUTDEG[s.y], 1);
    atomicAdd(&G_OUTDEG[s.z], 1);
    atomicAdd(&G_OUTDEG[s.w], 1);
    ushort4 r;
    r.x = (unsigned short)atomicAdd(&G_INDEG[d.x], 1);
    r.y = (unsigned short)atomicAdd(&G_INDEG[d.y], 1);
    r.z = (unsigned short)atomicAdd(&G_INDEG[d.z], 1);
    r.w = (unsigned short)atomicAdd(&G_INDEG[d.w], 1);
    *(ushort4*)(g_rank + i * 4) = r;
}

// ---------------- K0: h = feat @ W^T via HMMA; norms fused in epilogue ----
__global__ void __launch_bounds__(128) k_gemm(const float* __restrict__ feat,
                                              const float* __restrict__ W,
                                              const float* __restrict__ attn_l,
                                              const float* __restrict__ attn_r) {
    __shared__ __half sA[GEMM_TILE * APAD];
    __shared__ __half sB[OUT_F * APAD];
    int t = threadIdx.x;
    int warp = t >> 5, lane = t & 31;

#pragma unroll
    for (int i = 0; i < 16; i++) {
        int lin = t * 4 + i * 512;
        int o = lin >> 7, k = lin & 127;
        float4 w4 = __ldg((const float4*)(W + lin));
        *(__half2*)(sB + o * APAD + k)     = __floats2half2_rn(w4.x, w4.y);
        *(__half2*)(sB + o * APAD + k + 2) = __floats2half2_rn(w4.z, w4.w);
    }

    int m0 = warp * 16;
    int lr  = lane & 7;
    int grp = lane >> 3;
    int a_m = m0 + lr + ((grp & 1) ? 8 : 0);
    int a_k = (grp & 2) ? 8 : 0;
    unsigned aBase = smemu(sA) + (unsigned)(a_m * APAD + a_k) * 2;
    int b_n = lane & 7;
    int b_k = ((lane >> 3) & 1) ? 8 : 0;
    unsigned bBase = smemu(sB) + (unsigned)(b_n * APAD + b_k) * 2;

    int q  = lane & 3;
    int mr = lane >> 2;
    float2 alv[8], arv[8];
#pragma unroll
    for (int nt = 0; nt < 8; nt++) {
        alv[nt] = __ldg((const float2*)attn_l + nt * 4 + q);
        arv[nt] = __ldg((const float2*)attn_r + nt * 4 + q);
    }

    for (int tile = blockIdx.x; tile < GEMM_TILES; tile += gridDim.x) {
        int node0 = tile * GEMM_TILE;
        __syncthreads();
#pragma unroll
        for (int i = 0; i < 16; i++) {
            int lin = t * 4 + i * 512;
            int r = lin >> 7, k = lin & 127;
            int node = node0 + r; if (node > N_NODES - 1) node = N_NODES - 1;
            float4 f4 = __ldg((const float4*)(feat + (size_t)node * IN_F + k));
            *(__half2*)(sA + r * APAD + k)     = __floats2half2_rn(f4.x, f4.y);
            *(__half2*)(sA + r * APAD + k + 2) = __floats2half2_rn(f4.z, f4.w);
        }
        __syncthreads();

        float c[8][4];
#pragma unroll
        for (int nt = 0; nt < 8; nt++) { c[nt][0] = c[nt][1] = c[nt][2] = c[nt][3] = 0.f; }

#pragma unroll
        for (int ks = 0; ks < 8; ks++) {
            unsigned a0, a1, a2, a3;
            asm volatile("ldmatrix.sync.aligned.m8n8.x4.shared.b16 {%0,%1,%2,%3}, [%4];"
                         : "=r"(a0), "=r"(a1), "=r"(a2), "=r"(a3)
                         : "r"(aBase + ks * 32));
#pragma unroll
            for (int nt = 0; nt < 8; nt++) {
                unsigned b0, b1;
                asm volatile("ldmatrix.sync.aligned.m8n8.x2.shared.b16 {%0,%1}, [%2];"
                             : "=r"(b0), "=r"(b1)
                             : "r"(bBase + nt * (8 * APAD * 2) + ks * 32));
                asm volatile("mma.sync.aligned.m16n8k16.row.col.f32.f16.f16.f32 "
                             "{%0,%1,%2,%3}, {%4,%5,%6,%7}, {%8,%9}, {%0,%1,%2,%3};"
                             : "+f"(c[nt][0]), "+f"(c[nt][1]), "+f"(c[nt][2]), "+f"(c[nt][3])
                             : "r"(a0), "r"(a1), "r"(a2), "r"(a3), "r"(b0), "r"(b1));
            }
        }

        int nodeA = node0 + m0 + mr;
        int nodeB = nodeA + 8;
        bool va = nodeA < N_NODES, vb = nodeB < N_NODES;
        int odA = va ? __ldg(&G_OUTDEG[nodeA]) : 1;
        int odB = vb ? __ldg(&G_OUTDEG[nodeB]) : 1;
        float onA = rsqrtf((float)(odA < 1 ? 1 : odA));
        float onB = rsqrtf((float)(odB < 1 ? 1 : odB));
        float el0 = 0.f, er0 = 0.f, el1 = 0.f, er1 = 0.f;
        __half2* h2 = (__half2*)g_h;
#pragma unroll
        for (int nt = 0; nt < 8; nt++) {
            el0 += c[nt][0] * alv[nt].x + c[nt][1] * alv[nt].y;
            er0 += c[nt][0] * arv[nt].x + c[nt][1] * arv[nt].y;
            el1 += c[nt][2] * alv[nt].x + c[nt][3] * alv[nt].y;
            er1 += c[nt][2] * arv[nt].x + c[nt][3] * arv[nt].y;
            if (va) h2[(size_t)nodeA * 32 + nt * 4 + q] =
                __floats2half2_rn(c[nt][0] * onA, c[nt][1] * onA);
            if (vb) h2[(size_t)nodeB * 32 + nt * 4 + q] =
                __floats2half2_rn(c[nt][2] * onB, c[nt][3] * onB);
        }
#pragma unroll
        for (int o = 1; o <= 2; o <<= 1) {
            el0 += __shfl_xor_sync(0xffffffffu, el0, o);
            er0 += __shfl_xor_sync(0xffffffffu, er0, o);
            el1 += __shfl_xor_sync(0xffffffffu, el1, o);
            er1 += __shfl_xor_sync(0xffffffffu, er1, o);
        }
        if (q == 0) {
            if (va) {
                int id = __ldg(&G_INDEG[nodeA]); if (id < 1) id = 1;
                g_el[nodeA] = el0; g_er[nodeA] = er0;
                g_outnorm[nodeA] = onA;
                g_innorm[nodeA]  = sqrtf((float)id);
            }
            if (vb) {
                int id = __ldg(&G_INDEG[nodeB]); if (id < 1) id = 1;
                g_el[nodeB] = el1; g_er[nodeB] = er1;
                g_outnorm[nodeB] = onB;
                g_innorm[nodeB]  = sqrtf((float)id);
            }
        }
    }
}

// ---------------- K3: edge pass, 2 edges/thread, direct-slot fill ---------
__global__ void k_edge2(const int2* __restrict__ src2, const int2* __restrict__ dst2) {
    int i = blockIdx.x * blockDim.x + threadIdx.x;
    if (i >= N_EDGES / 2) return;
    int2 s = __ldg(src2 + i);
    int2 d = __ldg(dst2 + i);
    unsigned rr = __ldg((const unsigned*)g_rank + i);   // ranks 2i, 2i+1
    float ea = __ldg(&g_el[s.x]) + __ldg(&g_er[d.x]);
    float eb = __ldg(&g_el[s.y]) + __ldg(&g_er[d.y]);
    ea = ea > 0.f ? ea : NEG_SLOPE * ea;
    eb = eb > 0.f ? eb : NEG_SLOPE * eb;
    g_pack[(d.x << SLOT_LOG) + (int)(rr & 0xffffu)] = make_int2(s.x, __float_as_int(__expf(ea)));
    g_pack[(d.y << SLOT_LOG) + (int)(rr >> 16)]     = make_int2(s.y, __float_as_int(__expf(eb)));
}

// ---------------- K4: hop — 8 lanes/node, pipelined, int4 pack loads ------
__device__ __forceinline__ void fma8(float4& a0, float4& a1, float c, uint4 u) {
    float2 f;
    f = __half22float2(*(__half2*)&u.x); a0.x += c * f.x; a0.y += c * f.y;
    f = __half22float2(*(__half2*)&u.y); a0.z += c * f.x; a0.w += c * f.y;
    f = __half22float2(*(__half2*)&u.z); a1.x += c * f.x; a1.y += c * f.y;
    f = __half22float2(*(__half2*)&u.w); a1.z += c * f.x; a1.w += c * f.y;
}

// MODE 0: first hop  — denom = local sum of coefs; compute+cache scales
// MODE 1: middle hop — scale by cached scmid, write fp16 payload
// MODE 2: final hop  — scale by cached scfin, write fp32 output
template <int MODE>
__global__ void __launch_bounds__(256) k_hop(const __half* __restrict__ cur,
                                             void* __restrict__ nxt) {
    unsigned g = blockIdx.x * blockDim.x + threadIdx.x;
    unsigned n = g >> 3;
    if (n >= N_NODES) return;
    int lane = g & 7;
    int deg = __ldg(&G_INDEG[n]);
    int beg = (int)(n << SLOT_LOG);          // 1 KB-aligned row
    const uint4* cur4 = (const uint4*)cur;   // 8 uint4 per payload row
    float4 a0 = make_float4(0.f, 0.f, 0.f, 0.f);
    float4 a1 = make_float4(0.f, 0.f, 0.f, 0.f);
    float dsum = 0.f;
    int nfull = deg >> 2;
    const int4* pk = (const int4*)(g_pack + beg);   // 16B-aligned
    if (nfull > 0) {
        int4 ca = __ldg(pk);        // {s0, e0, s1, e1}
        int4 cb = __ldg(pk + 1);    // {s2, e2, s3, e3}
        for (int b = 1; b < nfull; b++) {
            int4 na = __ldg(pk + 2 * b);
            int4 nb = __ldg(pk + 2 * b + 1);
            uint4 u0 = __ldg(&cur4[(size_t)ca.x * 8 + lane]);
            uint4 u1 = __ldg(&cur4[(size_t)ca.z * 8 + lane]);
            uint4 u2 = __ldg(&cur4[(size_t)cb.x * 8 + lane]);
            uint4 u3 = __ldg(&cur4[(size_t)cb.z * 8 + lane]);
            float f0 = __int_as_float(ca.y), f1 = __int_as_float(ca.w);
            float f2 = __int_as_float(cb.y), f3 = __int_as_float(cb.w);
            if (MODE == 0) dsum += (f0 + f1) + (f2 + f3);
            fma8(a0, a1, f0, u0); fma8(a0, a1, f1, u1);
            fma8(a0, a1, f2, u2); fma8(a0, a1, f3, u3);
            ca = na; cb = nb;
        }
        uint4 u0 = __ldg(&cur4[(size_t)ca.x * 8 + lane]);
        uint4 u1 = __ldg(&cur4[(size_t)ca.z * 8 + lane]);
        uint4 u2 = __ldg(&cur4[(size_t)cb.x * 8 + lane]);
        uint4 u3 = __ldg(&cur4[(size_t)cb.z * 8 + lane]);
        float f0 = __int_as_float(ca.y), f1 = __int_as_float(ca.w);
        float f2 = __int_as_float(cb.y), f3 = __int_as_float(cb.w);
        if (MODE == 0) dsum += (f0 + f1) + (f2 + f3);
        fma8(a0, a1, f0, u0); fma8(a0, a1, f1, u1);
        fma8(a0, a1, f2, u2); fma8(a0, a1, f3, u3);
    }
    for (int p = beg + (nfull << 2), e = beg + deg; p < e; p++) {
        int2 k0 = __ldg(&g_pack[p]);
        uint4 u0 = __ldg(&cur4[(size_t)k0.x * 8 + lane]);
        float f0 = __int_as_float(k0.y);
        if (MODE == 0) dsum += f0;
        fma8(a0, a1, f0, u0);
    }
    float sc;
    if (MODE == 0) {
        float scfin = dsum > 0.f ? g_innorm[n] / dsum : 0.f;
        float scmid = scfin * g_outnorm[n];
        if (lane == 0) { g_innorm[n] = scmid; g_scfin[n] = scfin; }
        sc = scmid;
    } else if (MODE == 1) {
        sc = g_innorm[n];
    } else {
        sc = g_scfin[n];
    }
    a0.x *= sc; a0.y *= sc; a0.z *= sc; a0.w *= sc;
    a1.x *= sc; a1.y *= sc; a1.z *= sc; a1.w *= sc;
    if (MODE == 2) {
        ((float4*)nxt)[(size_t)n * 16 + lane * 2]     = a0;
        ((float4*)nxt)[(size_t)n * 16 + lane * 2 + 1] = a1;
    } else {
        __half2 h0 = __floats2half2_rn(a0.x, a0.y);
        __half2 h1 = __floats2half2_rn(a0.z, a0.w);
        __half2 h2 = __floats2half2_rn(a1.x, a1.y);
        __half2 h3 = __floats2half2_rn(a1.z, a1.w);
        uint4 u;
        u.x = *(unsigned*)&h0; u.y = *(unsigned*)&h1;
        u.z = *(unsigned*)&h2; u.w = *(unsigned*)&h3;
        ((uint4*)nxt)[(size_t)n * 8 + lane] = u;
    }
}

// ---------------- launch ----------------
extern "C" void kernel_launch(void* const* d_in, const int* in_sizes, int n_in,
                              void* d_out, int out_size) {
    const float* feat   = (const float*)d_in[0];
    const float* W      = (const float*)d_in[1];
    const float* attn_l = (const float*)d_in[2];
    const float* attn_r = (const float*)d_in[3];
    const int*   src    = (const int*)d_in[4];
    const int*   dst    = (const int*)d_in[5];
    float*       out    = (float*)d_out;

    void *p_zbuf, *p_x, *p_y, *p_h;
    cudaGetSymbolAddress(&p_zbuf, g_zbuf);
    cudaGetSymbolAddress(&p_x,    g_x);
    cudaGetSymbolAddress(&p_y,    g_y);
    cudaGetSymbolAddress(&p_h,    g_h);

    cudaMemsetAsync(p_zbuf, 0, ZBUF_BYTES);

    k_deg<<<(N_EDGES / 4 + 255) / 256, 256>>>((const int4*)src, (const int4*)dst);
    k_gemm<<<GEMM_GRID, 128>>>(feat, W, attn_l, attn_r);
    k_edge2<<<(N_EDGES / 2 + 255) / 256, 256>>>((const int2*)src, (const int2*)dst);

    const int hop_blocks = (N_NODES * 8 + 255) / 256;  // 3125
    k_hop<0><<<hop_blocks, 256>>>((const __half*)p_h, p_x);
    k_hop<1><<<hop_blocks, 256>>>((const __half*)p_x, p_y);
    k_hop<2><<<hop_blocks, 256>>>((const __half*)p_y, out);
}